// round 4
// baseline (speedup 1.0000x reference)
#include <cuda_runtime.h>
#include <cstdint>

// ---------------- problem constants ----------------
#define Bb      16
#define Ll      2048
#define DMODEL  256
#define DINNER  512
#define DSTATE  32
#define DCONV   4
#define DTRANK  16
#define HMLP    32
#define BINS    256
#define ML      (Bb*Ll)            // 32768 rows

__device__ __forceinline__ float fast_exp2(float x) {
    float r;
    asm("ex2.approx.ftz.f32 %0, %1;" : "=f"(r) : "f"(x));
    return r;
}

// ---------------- scratch (static device arrays; no allocation) ----------------
__device__ float  sXC  [(size_t)ML * DINNER];        // conv input (first half of xz)
__device__ float  sZ   [(size_t)ML * DINNER];        // gate z (second half of xz)
__device__ float  sU   [(size_t)ML * DINNER];        // silu(conv) contiguous for GEMM
__device__ float2 sDU  [(size_t)ML * DINNER];        // {dt, u} packed for scan
__device__ float  sDTLO[(size_t)ML * DTRANK];        // dt low-rank
__device__ float2 sBC  [(size_t)ML * DSTATE];        // {B, C} interleaved for scan
__device__ float  sY   [(size_t)ML * DINNER];        // gated scan output
__device__ float  sM   [(size_t)ML * DMODEL];        // mamba output
__device__ float  sH   [(size_t)ML * HMLP];          // mlp hidden

// epilogue modes
#define EPI_PLAIN   0
#define EPI_SPLITXZ 1   // n<512 -> aux0 (xc), else aux1 (z)
#define EPI_DBC     2   // n<16 -> C(dtlo); 16..47 -> aux0 .x; 48..79 -> .y
#define EPI_LEAKY   3   // +bias, leaky_relu(0.01)
#define EPI_SIGMOID 4   // +bias, sigmoid

// ---------------- big SGEMM: 128x128 tile, 8x8 per thread ----------------
// requires M%128==0, N%128==0, K%16==0
#define BM2 128
#define BN2 128
#define BK2 16

template<int E>
__global__ __launch_bounds__(256, 2)
void sgemm128_k(const float* __restrict__ A, const float* __restrict__ W,
                const float* __restrict__ bias, float* __restrict__ C,
                int M, int N, int K, float* __restrict__ aux0, float* __restrict__ aux1)
{
    __shared__ float As[BK2][BM2];
    __shared__ float Ws[BK2][BN2];

    const int tid = threadIdx.x;
    const int tx  = tid & 15;        // 0..15 -> col group (8 cols)
    const int ty  = tid >> 4;        // 0..15 -> row group (8 rows)
    const int m0  = blockIdx.y * BM2;
    const int n0  = blockIdx.x * BN2;

    float acc[8][8];
    #pragma unroll
    for (int i = 0; i < 8; ++i)
        #pragma unroll
        for (int j = 0; j < 8; ++j) acc[i][j] = 0.f;

    for (int k0 = 0; k0 < K; k0 += BK2) {
        // A tile: 128x16 = 512 float4, 2 per thread
        #pragma unroll
        for (int r = 0; r < 2; ++r) {
            int j   = tid + 256 * r;
            int row = j >> 2;
            int kq  = j & 3;
            float4 v = *(const float4*)(A + (size_t)(m0 + row) * K + k0 + kq * 4);
            As[kq*4+0][row] = v.x;
            As[kq*4+1][row] = v.y;
            As[kq*4+2][row] = v.z;
            As[kq*4+3][row] = v.w;
        }
        // W tile: 128x16 = 512 float4, 2 per thread
        #pragma unroll
        for (int r = 0; r < 2; ++r) {
            int j   = tid + 256 * r;
            int row = j >> 2;
            int kq  = j & 3;
            float4 v = *(const float4*)(W + (size_t)(n0 + row) * K + k0 + kq * 4);
            Ws[kq*4+0][row] = v.x;
            Ws[kq*4+1][row] = v.y;
            Ws[kq*4+2][row] = v.z;
            Ws[kq*4+3][row] = v.w;
        }
        __syncthreads();

        #pragma unroll
        for (int kk = 0; kk < BK2; ++kk) {
            float4 a0 = *(const float4*)&As[kk][ty * 8];
            float4 a1 = *(const float4*)&As[kk][ty * 8 + 4];
            float4 b0 = *(const float4*)&Ws[kk][tx * 8];
            float4 b1 = *(const float4*)&Ws[kk][tx * 8 + 4];
            float a[8] = {a0.x, a0.y, a0.z, a0.w, a1.x, a1.y, a1.z, a1.w};
            float b[8] = {b0.x, b0.y, b0.z, b0.w, b1.x, b1.y, b1.z, b1.w};
            #pragma unroll
            for (int i = 0; i < 8; ++i)
                #pragma unroll
                for (int j = 0; j < 8; ++j)
                    acc[i][j] = fmaf(a[i], b[j], acc[i][j]);
        }
        __syncthreads();
    }

    #pragma unroll
    for (int i = 0; i < 8; ++i) {
        int m = m0 + ty * 8 + i;
        #pragma unroll
        for (int j = 0; j < 8; ++j) {
            int n = n0 + tx * 8 + j;
            float v = acc[i][j];
            if (E == EPI_PLAIN) {
                C[(size_t)m * N + n] = v;
            } else if (E == EPI_SPLITXZ) {
                if (n < DINNER) aux0[(size_t)m * DINNER + n] = v;
                else            aux1[(size_t)m * DINNER + (n - DINNER)] = v;
            } else if (E == EPI_SIGMOID) {
                v += bias[n];
                v = 1.f / (1.f + __expf(-v));
                C[(size_t)m * N + n] = v;
            }
        }
    }
}

// ---------------- small SGEMM: 128x64 tile, 8x4 per thread (N arbitrary) ----------------
#define BM 128
#define BN 64
#define BKK 16

template<int E>
__global__ __launch_bounds__(256)
void sgemm_k(const float* __restrict__ A, const float* __restrict__ W,
             const float* __restrict__ bias, float* __restrict__ C,
             int M, int N, int K, float* __restrict__ aux0, float* __restrict__ aux1)
{
    __shared__ float As[BKK][BM];
    __shared__ float Ws[BKK][BN];

    const int tid = threadIdx.x;
    const int tx  = tid & 15;
    const int ty  = tid >> 4;
    const int m0  = blockIdx.y * BM;
    const int n0  = blockIdx.x * BN;

    float acc[8][4];
    #pragma unroll
    for (int i = 0; i < 8; ++i)
        #pragma unroll
        for (int j = 0; j < 4; ++j) acc[i][j] = 0.f;

    for (int k0 = 0; k0 < K; k0 += BKK) {
        #pragma unroll
        for (int r = 0; r < 2; ++r) {
            int j   = tid + 256 * r;
            int row = j >> 2;
            int kq  = j & 3;
            float4 v = *(const float4*)(A + (size_t)(m0 + row) * K + k0 + kq * 4);
            As[kq*4+0][row] = v.x;
            As[kq*4+1][row] = v.y;
            As[kq*4+2][row] = v.z;
            As[kq*4+3][row] = v.w;
        }
        {
            int row = tid >> 2;
            int kq  = tid & 3;
            float4 v = make_float4(0.f, 0.f, 0.f, 0.f);
            if (n0 + row < N)
                v = *(const float4*)(W + (size_t)(n0 + row) * K + k0 + kq * 4);
            Ws[kq*4+0][row] = v.x;
            Ws[kq*4+1][row] = v.y;
            Ws[kq*4+2][row] = v.z;
            Ws[kq*4+3][row] = v.w;
        }
        __syncthreads();

        #pragma unroll
        for (int kk = 0; kk < BKK; ++kk) {
            float4 a0 = *(const float4*)&As[kk][ty * 8];
            float4 a1 = *(const float4*)&As[kk][ty * 8 + 4];
            float4 wv = *(const float4*)&Ws[kk][tx * 4];
            float a[8] = {a0.x, a0.y, a0.z, a0.w, a1.x, a1.y, a1.z, a1.w};
            float w[4] = {wv.x, wv.y, wv.z, wv.w};
            #pragma unroll
            for (int i = 0; i < 8; ++i)
                #pragma unroll
                for (int j = 0; j < 4; ++j)
                    acc[i][j] = fmaf(a[i], w[j], acc[i][j]);
        }
        __syncthreads();
    }

    #pragma unroll
    for (int i = 0; i < 8; ++i) {
        int m = m0 + ty * 8 + i;
        #pragma unroll
        for (int j = 0; j < 4; ++j) {
            int n = n0 + tx * 4 + j;
            if (n >= N) continue;
            float v = acc[i][j];
            if (E == EPI_PLAIN) {
                C[(size_t)m * N + n] = v;
            } else if (E == EPI_DBC) {
                if (n < DTRANK)               C[(size_t)m * DTRANK + n] = v;
                else if (n < DTRANK + DSTATE) aux0[((size_t)m * DSTATE + (n - DTRANK)) * 2 + 0] = v;
                else                          aux0[((size_t)m * DSTATE + (n - DTRANK - DSTATE)) * 2 + 1] = v;
            } else if (E == EPI_LEAKY) {
                v += bias[n];
                v = (v > 0.f) ? v : 0.01f * v;
                C[(size_t)m * N + n] = v;
            }
        }
    }
}

// ---------------- depthwise causal conv + SiLU ----------------
__global__ __launch_bounds__(256)
void conv_silu_k(const float* __restrict__ cw, const float* __restrict__ cb)
{
    int idx = blockIdx.x * blockDim.x + threadIdx.x;     // < ML*DINNER
    int e   = idx & (DINNER - 1);
    int bl  = idx >> 9;
    int l   = bl & (Ll - 1);

    float acc = cb[e];
    #pragma unroll
    for (int k = 0; k < DCONV; ++k) {
        int ll = l - (DCONV - 1) + k;
        if (ll >= 0)
            acc = fmaf(sXC[(size_t)(bl - (DCONV - 1) + k) * DINNER + e], cw[e * DCONV + k], acc);
    }
    float u = acc / (1.f + __expf(-acc));   // silu
    sU[idx] = u;
    sDU[idx].y = u;
}

// ---------------- dt projection + softplus (W_dt in registers) ----------------
// block = 512 threads (one per d channel), each block processes 128 rows.
#define DT_ROWS 128
__global__ __launch_bounds__(512)
void dt_k(const float* __restrict__ Wdt, const float* __restrict__ bdt)
{
    const int d  = threadIdx.x;
    const int m0 = blockIdx.x * DT_ROWS;

    const float4* wp = (const float4*)(Wdt + d * DTRANK);
    const float4 w0 = wp[0], w1 = wp[1], w2 = wp[2], w3 = wp[3];
    const float  bb = bdt[d];

    __shared__ float lo[32 * DTRANK];    // 32 rows x 16

    for (int batch = 0; batch < DT_ROWS / 32; ++batch) {
        const int mb = m0 + batch * 32;
        __syncthreads();
        lo[d] = sDTLO[(size_t)mb * DTRANK + d];   // 512 contiguous floats = 32 rows
        __syncthreads();

        #pragma unroll 4
        for (int r = 0; r < 32; ++r) {
            const float4* lp = (const float4*)&lo[r * DTRANK];
            float4 l0 = lp[0], l1 = lp[1], l2 = lp[2], l3 = lp[3];
            float acc = bb;
            acc = fmaf(l0.x, w0.x, acc); acc = fmaf(l0.y, w0.y, acc);
            acc = fmaf(l0.z, w0.z, acc); acc = fmaf(l0.w, w0.w, acc);
            acc = fmaf(l1.x, w1.x, acc); acc = fmaf(l1.y, w1.y, acc);
            acc = fmaf(l1.z, w1.z, acc); acc = fmaf(l1.w, w1.w, acc);
            acc = fmaf(l2.x, w2.x, acc); acc = fmaf(l2.y, w2.y, acc);
            acc = fmaf(l2.z, w2.z, acc); acc = fmaf(l2.w, w2.w, acc);
            acc = fmaf(l3.x, w3.x, acc); acc = fmaf(l3.y, w3.y, acc);
            acc = fmaf(l3.z, w3.z, acc); acc = fmaf(l3.w, w3.w, acc);

            float sp = (acc > 20.f) ? acc : log1pf(__expf(acc));
            sDU[(size_t)(mb + r) * DINNER + d].x = sp;
        }
    }
}

// ---------------- selective scan (warp per (b,d), lane = state) ----------------
__global__ __launch_bounds__(256)
void scan_k(const float* __restrict__ A_log, const float* __restrict__ Dp)
{
    const int b = blockIdx.y;
    const int d = blockIdx.x * 8 + (threadIdx.x >> 5);
    const int s = threadIdx.x & 31;

    const float A2 = -__expf(A_log[d * DSTATE + s]) * 1.4426950408889634f;
    const float Dd = Dp[d];

    const float2* __restrict__ du = sDU + (size_t)b * Ll * DINNER + d;
    const float2* __restrict__ bc = sBC + (size_t)b * Ll * DSTATE + s;
    const float*  __restrict__ zp = sZ  + (size_t)b * Ll * DINNER + d;
    float*        __restrict__ yp = sY  + (size_t)b * Ll * DINNER + d;

    float h = 0.f;
    #pragma unroll 4
    for (int l = 0; l < Ll; ++l) {
        float2 duv = du[(size_t)l * DINNER];   // uniform across warp
        float2 bcv = bc[(size_t)l * DSTATE];   // per-lane {B, C}
        float  zv  = zp[(size_t)l * DINNER];   // uniform

        float e   = fast_exp2(duv.x * A2);
        float dtu = duv.x * duv.y;
        h = fmaf(h, e, dtu * bcv.x);
        float y = h * bcv.y;

        y += __shfl_xor_sync(0xffffffffu, y, 16);
        y += __shfl_xor_sync(0xffffffffu, y, 8);
        y += __shfl_xor_sync(0xffffffffu, y, 4);
        y += __shfl_xor_sync(0xffffffffu, y, 2);
        y += __shfl_xor_sync(0xffffffffu, y, 1);

        if (s == 0) {
            y = fmaf(duv.y, Dd, y);
            float sg = 1.f / (1.f + __expf(-zv));
            yp[(size_t)l * DINNER] = y * (zv * sg);
        }
    }
}

// ---------------- launch ----------------
extern "C" void kernel_launch(void* const* d_in, const int* in_sizes, int n_in,
                              void* d_out, int out_size)
{
    const float* x      = (const float*)d_in[0];
    const float* W_in   = (const float*)d_in[1];
    const float* conv_w = (const float*)d_in[2];
    const float* conv_b = (const float*)d_in[3];
    const float* W_xprj = (const float*)d_in[4];
    const float* W_dt   = (const float*)d_in[5];
    const float* b_dt   = (const float*)d_in[6];
    const float* A_log  = (const float*)d_in[7];
    const float* Dvec   = (const float*)d_in[8];
    const float* W_out  = (const float*)d_in[9];
    const float* W_ff1  = (const float*)d_in[10];
    const float* b_ff1  = (const float*)d_in[11];
    const float* W_ff2  = (const float*)d_in[12];
    const float* b_ff2  = (const float*)d_in[13];
    float* out = (float*)d_out;

    float *pXC, *pZ, *pU, *pDTLO, *pY, *pM, *pH;
    float2 *pDU, *pBC;
    cudaGetSymbolAddress((void**)&pXC,   sXC);
    cudaGetSymbolAddress((void**)&pZ,    sZ);
    cudaGetSymbolAddress((void**)&pU,    sU);
    cudaGetSymbolAddress((void**)&pDU,   sDU);
    cudaGetSymbolAddress((void**)&pDTLO, sDTLO);
    cudaGetSymbolAddress((void**)&pBC,   sBC);
    cudaGetSymbolAddress((void**)&pY,    sY);
    cudaGetSymbolAddress((void**)&pM,    sM);
    cudaGetSymbolAddress((void**)&pH,    sH);

    // 1) xz = x @ W_in^T  -> split into xc / z   (N=1024, K=256)
    {
        dim3 g((2 * DINNER) / BN2, ML / BM2);
        sgemm128_k<EPI_SPLITXZ><<<g, 256>>>(x, W_in, nullptr, nullptr,
                                            ML, 2 * DINNER, DMODEL, pXC, pZ);
    }
    // 2) depthwise conv + silu -> u
    conv_silu_k<<<(ML * DINNER) / 256, 256>>>(conv_w, conv_b);

    // 3) dbc = u @ W_xproj^T -> scatter dtlo / {B,C}   (N=80, K=512)
    {
        dim3 g((DTRANK + 2 * DSTATE + BN - 1) / BN, ML / BM);
        sgemm_k<EPI_DBC><<<g, 256>>>(pU, W_xprj, nullptr, pDTLO,
                                     ML, DTRANK + 2 * DSTATE, DINNER, (float*)pBC, nullptr);
    }
    // 4) dt = softplus(dtlo @ W_dt^T + b_dt)
    dt_k<<<ML / DT_ROWS, DINNER>>>(W_dt, b_dt);

    // 5) selective scan (+D skip, silu(z) gate)
    {
        dim3 g(DINNER / 8, Bb);
        scan_k<<<g, 256>>>(A_log, Dvec);
    }
    // 6) m = y @ W_out^T   (N=256, K=512)
    {
        dim3 g(DMODEL / BN2, ML / BM2);
        sgemm128_k<EPI_PLAIN><<<g, 256>>>(pY, W_out, nullptr, pM,
                                          ML, DMODEL, DINNER, nullptr, nullptr);
    }
    // 7) h = leaky_relu(m @ W_ff1^T + b_ff1)   (N=32, K=256)
    {
        dim3 g((HMLP + BN - 1) / BN, ML / BM);
        sgemm_k<EPI_LEAKY><<<g, 256>>>(pM, W_ff1, b_ff1, pH,
                                       ML, HMLP, DMODEL, nullptr, nullptr);
    }
    // 8) out = sigmoid(h @ W_ff2^T + b_ff2)   (N=256, K=32)
    {
        dim3 g(BINS / BN2, ML / BM2);
        sgemm128_k<EPI_SIGMOID><<<g, 256>>>(pH, W_ff2, b_ff2, out,
                                            ML, BINS, HMLP, nullptr, nullptr);
    }
}

// round 5
// speedup vs baseline: 1.2723x; 1.2723x over previous
#include <cuda_runtime.h>
#include <cstdint>

// ---------------- problem constants ----------------
#define Bb      16
#define Ll      2048
#define DMODEL  256
#define DINNER  512
#define DSTATE  32
#define DCONV   4
#define DTRANK  16
#define HMLP    32
#define BINS    256
#define ML      (Bb*Ll)            // 32768 rows

__device__ __forceinline__ float fast_exp2(float x) {
    float r;
    asm("ex2.approx.ftz.f32 %0, %1;" : "=f"(r) : "f"(x));
    return r;
}
__device__ __forceinline__ uint32_t f2tf32(float x) {
    uint32_t r;
    asm("cvt.rna.tf32.f32 %0, %1;" : "=r"(r) : "f"(x));
    return r;
}

// ---------------- scratch (static device arrays; no allocation) ----------------
__device__ float  sXC  [(size_t)ML * DINNER];        // conv input (first half of xz)
__device__ float  sZ   [(size_t)ML * DINNER];        // gate z (second half of xz)
__device__ float  sU   [(size_t)ML * DINNER];        // silu(conv) contiguous for GEMM
__device__ float2 sDU  [(size_t)ML * DINNER];        // {dt, u} packed for scan
__device__ float  sDTLO[(size_t)ML * DTRANK];        // dt low-rank
__device__ float2 sBC  [(size_t)ML * DSTATE];        // {B, C} interleaved for scan
__device__ float  sY   [(size_t)ML * DINNER];        // gated scan output
__device__ float  sM   [(size_t)ML * DMODEL];        // mamba output
__device__ float  sH   [(size_t)ML * HMLP];          // mlp hidden
__device__ float  sWXP [128 * DINNER];               // W_xproj padded 80->128 rows
__device__ float  sWF1P[128 * DMODEL];               // W_ff1 padded 32->128 rows

// epilogue modes
#define EPI_PLAIN   0
#define EPI_SPLITXZ 1   // col<512 -> aux0 (xc), else aux1 (z)
#define EPI_DBC     2   // col<16 -> C(dtlo); 16..47 -> aux0 .x; 48..79 -> .y; else drop
#define EPI_LEAKY   3   // +bias, leaky_relu(0.01); col>=realN dropped
#define EPI_SIGMOID 4   // +bias, sigmoid

// ---------------- tf32 tensor-core GEMM: C[m,n] = sum_k A[m,k]*W[n,k] ----------------
// tile 128x128x32, 8 warps (2Mx4N), warp tile 64x32 via mma.sync m16n8k8 tf32.
// requires M%128==0, N%128==0 (padded), K%32==0.
#define TBM 128
#define TBN 128
#define TBK 32
#define SSTR 36   // smem row stride in words (conflict-free: bank = 4g+t)

template<int E>
__global__ __launch_bounds__(256)
void tgemm_k(const float* __restrict__ A, const float* __restrict__ W,
             const float* __restrict__ bias, float* __restrict__ C,
             int M, int N, int K, int realN,
             float* __restrict__ aux0, float* __restrict__ aux1)
{
    __shared__ uint32_t As[TBM][SSTR];   // [m][k] tf32 bits
    __shared__ uint32_t Ws[TBN][SSTR];   // [n][k] tf32 bits

    const int tid  = threadIdx.x;
    const int lane = tid & 31;
    const int wid  = tid >> 5;
    const int wm   = wid & 1;     // 0..1  -> 64-row slice
    const int wn   = wid >> 1;    // 0..3  -> 32-col slice
    const int m0   = blockIdx.y * TBM;
    const int n0   = blockIdx.x * TBN;
    const int g    = lane >> 2;   // 0..7
    const int t    = lane & 3;    // 0..3

    float acc[4][4][4];
    #pragma unroll
    for (int i = 0; i < 4; ++i)
        #pragma unroll
        for (int j = 0; j < 4; ++j)
            #pragma unroll
            for (int q = 0; q < 4; ++q) acc[i][j][q] = 0.f;

    for (int k0 = 0; k0 < K; k0 += TBK) {
        // fill A tile: 128 rows x 8 float4
        #pragma unroll
        for (int r = 0; r < 4; ++r) {
            int j   = r * 256 + tid;
            int row = j >> 3;
            int kq  = j & 7;
            float4 v = *(const float4*)(A + (size_t)(m0 + row) * K + k0 + kq * 4);
            uint32_t* p = &As[row][kq * 4];
            p[0] = f2tf32(v.x); p[1] = f2tf32(v.y);
            p[2] = f2tf32(v.z); p[3] = f2tf32(v.w);
        }
        // fill W tile
        #pragma unroll
        for (int r = 0; r < 4; ++r) {
            int j   = r * 256 + tid;
            int row = j >> 3;
            int kq  = j & 7;
            float4 v = *(const float4*)(W + (size_t)(n0 + row) * K + k0 + kq * 4);
            uint32_t* p = &Ws[row][kq * 4];
            p[0] = f2tf32(v.x); p[1] = f2tf32(v.y);
            p[2] = f2tf32(v.z); p[3] = f2tf32(v.w);
        }
        __syncthreads();

        #pragma unroll
        for (int k8 = 0; k8 < 4; ++k8) {
            const int kc = k8 * 8 + t;
            uint32_t a[4][4];
            #pragma unroll
            for (int mf = 0; mf < 4; ++mf) {
                const int r0 = wm * 64 + mf * 16 + g;
                a[mf][0] = As[r0    ][kc];
                a[mf][1] = As[r0 + 8][kc];
                a[mf][2] = As[r0    ][kc + 4];
                a[mf][3] = As[r0 + 8][kc + 4];
            }
            uint32_t b[4][2];
            #pragma unroll
            for (int nf = 0; nf < 4; ++nf) {
                const int rb = wn * 32 + nf * 8 + g;
                b[nf][0] = Ws[rb][kc];
                b[nf][1] = Ws[rb][kc + 4];
            }
            #pragma unroll
            for (int mf = 0; mf < 4; ++mf)
                #pragma unroll
                for (int nf = 0; nf < 4; ++nf) {
                    float* d = acc[mf][nf];
                    asm volatile(
                        "mma.sync.aligned.m16n8k8.row.col.f32.tf32.tf32.f32 "
                        "{%0,%1,%2,%3}, {%4,%5,%6,%7}, {%8,%9}, {%0,%1,%2,%3};\n"
                        : "+f"(d[0]), "+f"(d[1]), "+f"(d[2]), "+f"(d[3])
                        : "r"(a[mf][0]), "r"(a[mf][1]), "r"(a[mf][2]), "r"(a[mf][3]),
                          "r"(b[nf][0]), "r"(b[nf][1]));
                }
        }
        __syncthreads();
    }

    // epilogue: c0/c1 at (row, col), (row, col+1); c2/c3 at row+8
    #pragma unroll
    for (int mf = 0; mf < 4; ++mf) {
        const int rowb = m0 + wm * 64 + mf * 16 + g;
        #pragma unroll
        for (int nf = 0; nf < 4; ++nf) {
            const int colb = n0 + wn * 32 + nf * 8 + 2 * t;
            #pragma unroll
            for (int half = 0; half < 2; ++half) {
                const int m = rowb + half * 8;
                #pragma unroll
                for (int q = 0; q < 2; ++q) {
                    const int col = colb + q;
                    float v = acc[mf][nf][half * 2 + q];
                    if (E == EPI_PLAIN) {
                        C[(size_t)m * N + col] = v;
                    } else if (E == EPI_SPLITXZ) {
                        if (col < DINNER) aux0[(size_t)m * DINNER + col] = v;
                        else              aux1[(size_t)m * DINNER + (col - DINNER)] = v;
                    } else if (E == EPI_DBC) {
                        if (col < DTRANK)
                            C[(size_t)m * DTRANK + col] = v;
                        else if (col < DTRANK + DSTATE)
                            aux0[((size_t)m * DSTATE + (col - DTRANK)) * 2 + 0] = v;
                        else if (col < DTRANK + 2 * DSTATE)
                            aux0[((size_t)m * DSTATE + (col - DTRANK - DSTATE)) * 2 + 1] = v;
                    } else if (E == EPI_LEAKY) {
                        if (col < realN) {
                            v += bias[col];
                            v = (v > 0.f) ? v : 0.01f * v;
                            C[(size_t)m * realN + col] = v;
                        }
                    } else if (E == EPI_SIGMOID) {
                        v += bias[col];
                        v = 1.f / (1.f + __expf(-v));
                        C[(size_t)m * N + col] = v;
                    }
                }
            }
        }
    }
}

// ---------------- weight pad kernels ----------------
__global__ void pad_wx_k(const float* __restrict__ Wx)
{
    int idx = blockIdx.x * blockDim.x + threadIdx.x;   // < 128*512
    int n = idx >> 9, k = idx & 511;
    sWXP[idx] = (n < DTRANK + 2 * DSTATE) ? Wx[n * DINNER + k] : 0.f;
}
__global__ void pad_wf1_k(const float* __restrict__ Wf1)
{
    int idx = blockIdx.x * blockDim.x + threadIdx.x;   // < 128*256
    int n = idx >> 8, k = idx & 255;
    sWF1P[idx] = (n < HMLP) ? Wf1[n * DMODEL + k] : 0.f;
}

// ---------------- depthwise causal conv + SiLU ----------------
__global__ __launch_bounds__(256)
void conv_silu_k(const float* __restrict__ cw, const float* __restrict__ cb)
{
    int idx = blockIdx.x * blockDim.x + threadIdx.x;     // < ML*DINNER
    int e   = idx & (DINNER - 1);
    int bl  = idx >> 9;
    int l   = bl & (Ll - 1);

    float acc = cb[e];
    #pragma unroll
    for (int k = 0; k < DCONV; ++k) {
        int ll = l - (DCONV - 1) + k;
        if (ll >= 0)
            acc = fmaf(sXC[(size_t)(bl - (DCONV - 1) + k) * DINNER + e], cw[e * DCONV + k], acc);
    }
    float u = acc / (1.f + __expf(-acc));   // silu
    sU[idx] = u;
    sDU[idx].y = u;
}

// ---------------- dt projection + softplus (W_dt in registers) ----------------
#define DT_ROWS 128
__global__ __launch_bounds__(512)
void dt_k(const float* __restrict__ Wdt, const float* __restrict__ bdt)
{
    const int d  = threadIdx.x;
    const int m0 = blockIdx.x * DT_ROWS;

    const float4* wp = (const float4*)(Wdt + d * DTRANK);
    const float4 w0 = wp[0], w1 = wp[1], w2 = wp[2], w3 = wp[3];
    const float  bb = bdt[d];

    __shared__ float lo[32 * DTRANK];

    for (int batch = 0; batch < DT_ROWS / 32; ++batch) {
        const int mb = m0 + batch * 32;
        __syncthreads();
        lo[d] = sDTLO[(size_t)mb * DTRANK + d];
        __syncthreads();

        #pragma unroll 4
        for (int r = 0; r < 32; ++r) {
            const float4* lp = (const float4*)&lo[r * DTRANK];
            float4 l0 = lp[0], l1 = lp[1], l2 = lp[2], l3 = lp[3];
            float acc = bb;
            acc = fmaf(l0.x, w0.x, acc); acc = fmaf(l0.y, w0.y, acc);
            acc = fmaf(l0.z, w0.z, acc); acc = fmaf(l0.w, w0.w, acc);
            acc = fmaf(l1.x, w1.x, acc); acc = fmaf(l1.y, w1.y, acc);
            acc = fmaf(l1.z, w1.z, acc); acc = fmaf(l1.w, w1.w, acc);
            acc = fmaf(l2.x, w2.x, acc); acc = fmaf(l2.y, w2.y, acc);
            acc = fmaf(l2.z, w2.z, acc); acc = fmaf(l2.w, w2.w, acc);
            acc = fmaf(l3.x, w3.x, acc); acc = fmaf(l3.y, w3.y, acc);
            acc = fmaf(l3.z, w3.z, acc); acc = fmaf(l3.w, w3.w, acc);

            float sp = (acc > 20.f) ? acc : log1pf(__expf(acc));
            sDU[(size_t)(mb + r) * DINNER + d].x = sp;
        }
    }
}

// ---------------- selective scan (warp per (b,d), lane = state) ----------------
__global__ __launch_bounds__(256)
void scan_k(const float* __restrict__ A_log, const float* __restrict__ Dp)
{
    const int b = blockIdx.y;
    const int d = blockIdx.x * 8 + (threadIdx.x >> 5);
    const int s = threadIdx.x & 31;

    const float A2 = -__expf(A_log[d * DSTATE + s]) * 1.4426950408889634f;
    const float Dd = Dp[d];

    const float2* __restrict__ du = sDU + (size_t)b * Ll * DINNER + d;
    const float2* __restrict__ bc = sBC + (size_t)b * Ll * DSTATE + s;
    const float*  __restrict__ zp = sZ  + (size_t)b * Ll * DINNER + d;
    float*        __restrict__ yp = sY  + (size_t)b * Ll * DINNER + d;

    float h = 0.f;
    #pragma unroll 4
    for (int l = 0; l < Ll; ++l) {
        float2 duv = du[(size_t)l * DINNER];   // uniform across warp
        float2 bcv = bc[(size_t)l * DSTATE];   // per-lane {B, C}
        float  zv  = zp[(size_t)l * DINNER];   // uniform

        float e   = fast_exp2(duv.x * A2);
        float dtu = duv.x * duv.y;
        h = fmaf(h, e, dtu * bcv.x);
        float y = h * bcv.y;

        y += __shfl_xor_sync(0xffffffffu, y, 16);
        y += __shfl_xor_sync(0xffffffffu, y, 8);
        y += __shfl_xor_sync(0xffffffffu, y, 4);
        y += __shfl_xor_sync(0xffffffffu, y, 2);
        y += __shfl_xor_sync(0xffffffffu, y, 1);

        if (s == 0) {
            y = fmaf(duv.y, Dd, y);
            float sg = 1.f / (1.f + __expf(-zv));
            yp[(size_t)l * DINNER] = y * (zv * sg);
        }
    }
}

// ---------------- launch ----------------
extern "C" void kernel_launch(void* const* d_in, const int* in_sizes, int n_in,
                              void* d_out, int out_size)
{
    const float* x      = (const float*)d_in[0];
    const float* W_in   = (const float*)d_in[1];
    const float* conv_w = (const float*)d_in[2];
    const float* conv_b = (const float*)d_in[3];
    const float* W_xprj = (const float*)d_in[4];
    const float* W_dt   = (const float*)d_in[5];
    const float* b_dt   = (const float*)d_in[6];
    const float* A_log  = (const float*)d_in[7];
    const float* Dvec   = (const float*)d_in[8];
    const float* W_out  = (const float*)d_in[9];
    const float* W_ff1  = (const float*)d_in[10];
    const float* b_ff1  = (const float*)d_in[11];
    const float* W_ff2  = (const float*)d_in[12];
    const float* b_ff2  = (const float*)d_in[13];
    float* out = (float*)d_out;

    float *pXC, *pZ, *pU, *pDTLO, *pY, *pM, *pH, *pWXP, *pWF1P;
    float2 *pDU, *pBC;
    cudaGetSymbolAddress((void**)&pXC,   sXC);
    cudaGetSymbolAddress((void**)&pZ,    sZ);
    cudaGetSymbolAddress((void**)&pU,    sU);
    cudaGetSymbolAddress((void**)&pDU,   sDU);
    cudaGetSymbolAddress((void**)&pDTLO, sDTLO);
    cudaGetSymbolAddress((void**)&pBC,   sBC);
    cudaGetSymbolAddress((void**)&pY,    sY);
    cudaGetSymbolAddress((void**)&pM,    sM);
    cudaGetSymbolAddress((void**)&pH,    sH);
    cudaGetSymbolAddress((void**)&pWXP,  sWXP);
    cudaGetSymbolAddress((void**)&pWF1P, sWF1P);

    // 0) pad small weights to N=128
    pad_wx_k <<<(128 * DINNER) / 256, 256>>>(W_xprj);
    pad_wf1_k<<<(128 * DMODEL) / 256, 256>>>(W_ff1);

    // 1) xz = x @ W_in^T -> split xc/z   (N=1024, K=256)
    {
        dim3 g((2 * DINNER) / TBN, ML / TBM);
        tgemm_k<EPI_SPLITXZ><<<g, 256>>>(x, W_in, nullptr, nullptr,
                                         ML, 2 * DINNER, DMODEL, 2 * DINNER, pXC, pZ);
    }
    // 2) depthwise conv + silu -> u
    conv_silu_k<<<(ML * DINNER) / 256, 256>>>(conv_w, conv_b);

    // 3) dbc = u @ Wxproj^T -> dtlo / {B,C}   (N=128 padded, K=512)
    {
        dim3 g(1, ML / TBM);
        tgemm_k<EPI_DBC><<<g, 256>>>(pU, pWXP, nullptr, pDTLO,
                                     ML, 128, DINNER, DTRANK + 2 * DSTATE, (float*)pBC, nullptr);
    }
    // 4) dt = softplus(dtlo @ W_dt^T + b_dt)
    dt_k<<<ML / DT_ROWS, DINNER>>>(W_dt, b_dt);

    // 5) selective scan (+D skip, silu(z) gate)
    {
        dim3 g(DINNER / 8, Bb);
        scan_k<<<g, 256>>>(A_log, Dvec);
    }
    // 6) m = y @ W_out^T   (N=256, K=512)
    {
        dim3 g(DMODEL / TBN, ML / TBM);
        tgemm_k<EPI_PLAIN><<<g, 256>>>(pY, W_out, nullptr, pM,
                                       ML, DMODEL, DINNER, DMODEL, nullptr, nullptr);
    }
    // 7) h = leaky_relu(m @ W_ff1^T + b_ff1)   (N=128 padded, K=256, realN=32)
    {
        dim3 g(1, ML / TBM);
        tgemm_k<EPI_LEAKY><<<g, 256>>>(pM, pWF1P, b_ff1, pH,
                                       ML, 128, DMODEL, HMLP, nullptr, nullptr);
    }
    // 8) out = sigmoid(h @ W_ff2^T + b_ff2)   (N=256, K=32)
    {
        dim3 g(BINS / TBN, ML / TBM);
        tgemm_k<EPI_SIGMOID><<<g, 256>>>(pH, W_ff2, b_ff2, out,
                                         ML, BINS, HMLP, BINS, nullptr, nullptr);
    }
}

// round 6
// speedup vs baseline: 2.1986x; 1.7280x over previous
#include <cuda_runtime.h>
#include <cstdint>

// ---------------- problem constants ----------------
#define Bb      16
#define Ll      2048
#define DMODEL  256
#define DINNER  512
#define DSTATE  32
#define DCONV   4
#define DTRANK  16
#define HMLP    32
#define BINS    256
#define ML      (Bb*Ll)            // 32768 rows

__device__ __forceinline__ float fast_exp2(float x) {
    float r;
    asm("ex2.approx.ftz.f32 %0, %1;" : "=f"(r) : "f"(x));
    return r;
}
__device__ __forceinline__ uint32_t f2tf32(float x) {
    uint32_t r;
    asm("cvt.rna.tf32.f32 %0, %1;" : "=r"(r) : "f"(x));
    return r;
}

// ---------------- scratch (static device arrays; no allocation) ----------------
// +1 row padding on scan-read arrays so the software prefetch can read one row past.
__device__ float  sXC  [(size_t)ML * DINNER];
__device__ float  sZ   [(size_t)(ML + 1) * DINNER];
__device__ float  sU   [(size_t)ML * DINNER];
__device__ float2 sDU  [(size_t)(ML + 1) * DINNER];  // {dt, u}
__device__ float  sDTLO[(size_t)ML * DTRANK];
__device__ float2 sBC  [(size_t)(ML + 1) * DSTATE];  // {B, C} interleaved
__device__ float  sY   [(size_t)ML * DINNER];
__device__ float  sM   [(size_t)ML * DMODEL];
__device__ float  sH   [(size_t)ML * HMLP];
__device__ float  sWXP [128 * DINNER];
__device__ float  sWF1P[128 * DMODEL];

// epilogue modes
#define EPI_PLAIN   0
#define EPI_SPLITXZ 1
#define EPI_DBC     2
#define EPI_LEAKY   3
#define EPI_SIGMOID 4

// ---------------- tf32 tensor-core GEMM ----------------
#define TBM 128
#define TBN 128
#define TBK 32
#define SSTR 36

template<int E>
__global__ __launch_bounds__(256, 2)
void tgemm_k(const float* __restrict__ A, const float* __restrict__ W,
             const float* __restrict__ bias, float* __restrict__ C,
             int M, int N, int K, int realN,
             float* __restrict__ aux0, float* __restrict__ aux1)
{
    __shared__ uint32_t As[TBM][SSTR];
    __shared__ uint32_t Ws[TBN][SSTR];

    const int tid  = threadIdx.x;
    const int lane = tid & 31;
    const int wid  = tid >> 5;
    const int wm   = wid & 1;
    const int wn   = wid >> 1;
    const int m0   = blockIdx.y * TBM;
    const int n0   = blockIdx.x * TBN;
    const int g    = lane >> 2;
    const int t    = lane & 3;

    float acc[4][4][4];
    #pragma unroll
    for (int i = 0; i < 4; ++i)
        #pragma unroll
        for (int j = 0; j < 4; ++j)
            #pragma unroll
            for (int q = 0; q < 4; ++q) acc[i][j][q] = 0.f;

    for (int k0 = 0; k0 < K; k0 += TBK) {
        #pragma unroll
        for (int r = 0; r < 4; ++r) {
            int j   = r * 256 + tid;
            int row = j >> 3;
            int kq  = j & 7;
            float4 v = *(const float4*)(A + (size_t)(m0 + row) * K + k0 + kq * 4);
            uint32_t* p = &As[row][kq * 4];
            p[0] = f2tf32(v.x); p[1] = f2tf32(v.y);
            p[2] = f2tf32(v.z); p[3] = f2tf32(v.w);
        }
        #pragma unroll
        for (int r = 0; r < 4; ++r) {
            int j   = r * 256 + tid;
            int row = j >> 3;
            int kq  = j & 7;
            float4 v = *(const float4*)(W + (size_t)(n0 + row) * K + k0 + kq * 4);
            uint32_t* p = &Ws[row][kq * 4];
            p[0] = f2tf32(v.x); p[1] = f2tf32(v.y);
            p[2] = f2tf32(v.z); p[3] = f2tf32(v.w);
        }
        __syncthreads();

        #pragma unroll
        for (int k8 = 0; k8 < 4; ++k8) {
            const int kc = k8 * 8 + t;
            uint32_t a[4][4];
            #pragma unroll
            for (int mf = 0; mf < 4; ++mf) {
                const int r0 = wm * 64 + mf * 16 + g;
                a[mf][0] = As[r0    ][kc];
                a[mf][1] = As[r0 + 8][kc];
                a[mf][2] = As[r0    ][kc + 4];
                a[mf][3] = As[r0 + 8][kc + 4];
            }
            uint32_t b[4][2];
            #pragma unroll
            for (int nf = 0; nf < 4; ++nf) {
                const int rb = wn * 32 + nf * 8 + g;
                b[nf][0] = Ws[rb][kc];
                b[nf][1] = Ws[rb][kc + 4];
            }
            #pragma unroll
            for (int mf = 0; mf < 4; ++mf)
                #pragma unroll
                for (int nf = 0; nf < 4; ++nf) {
                    float* d = acc[mf][nf];
                    asm volatile(
                        "mma.sync.aligned.m16n8k8.row.col.f32.tf32.tf32.f32 "
                        "{%0,%1,%2,%3}, {%4,%5,%6,%7}, {%8,%9}, {%0,%1,%2,%3};\n"
                        : "+f"(d[0]), "+f"(d[1]), "+f"(d[2]), "+f"(d[3])
                        : "r"(a[mf][0]), "r"(a[mf][1]), "r"(a[mf][2]), "r"(a[mf][3]),
                          "r"(b[nf][0]), "r"(b[nf][1]));
                }
        }
        __syncthreads();
    }

    // epilogue (paired 8B stores where layout allows; all split points are even)
    #pragma unroll
    for (int mf = 0; mf < 4; ++mf) {
        const int rowb = m0 + wm * 64 + mf * 16 + g;
        #pragma unroll
        for (int nf = 0; nf < 4; ++nf) {
            const int colb = n0 + wn * 32 + nf * 8 + 2 * t;
            #pragma unroll
            for (int half = 0; half < 2; ++half) {
                const int m = rowb + half * 8;
                float v0 = acc[mf][nf][half * 2 + 0];
                float v1 = acc[mf][nf][half * 2 + 1];
                if (E == EPI_PLAIN) {
                    *(float2*)&C[(size_t)m * N + colb] = make_float2(v0, v1);
                } else if (E == EPI_SPLITXZ) {
                    if (colb < DINNER)
                        *(float2*)&aux0[(size_t)m * DINNER + colb] = make_float2(v0, v1);
                    else
                        *(float2*)&aux1[(size_t)m * DINNER + (colb - DINNER)] = make_float2(v0, v1);
                } else if (E == EPI_DBC) {
                    #pragma unroll
                    for (int q = 0; q < 2; ++q) {
                        const int col = colb + q;
                        float v = q ? v1 : v0;
                        if (col < DTRANK)
                            C[(size_t)m * DTRANK + col] = v;
                        else if (col < DTRANK + DSTATE)
                            aux0[((size_t)m * DSTATE + (col - DTRANK)) * 2 + 0] = v;
                        else if (col < DTRANK + 2 * DSTATE)
                            aux0[((size_t)m * DSTATE + (col - DTRANK - DSTATE)) * 2 + 1] = v;
                    }
                } else if (E == EPI_LEAKY) {
                    if (colb + 1 < realN) {
                        v0 += bias[colb];     v0 = (v0 > 0.f) ? v0 : 0.01f * v0;
                        v1 += bias[colb + 1]; v1 = (v1 > 0.f) ? v1 : 0.01f * v1;
                        *(float2*)&C[(size_t)m * realN + colb] = make_float2(v0, v1);
                    }
                } else if (E == EPI_SIGMOID) {
                    v0 += bias[colb];     v0 = 1.f / (1.f + __expf(-v0));
                    v1 += bias[colb + 1]; v1 = 1.f / (1.f + __expf(-v1));
                    *(float2*)&C[(size_t)m * N + colb] = make_float2(v0, v1);
                }
            }
        }
    }
}

// ---------------- weight pad kernels ----------------
__global__ void pad_wx_k(const float* __restrict__ Wx)
{
    int idx = blockIdx.x * blockDim.x + threadIdx.x;
    int n = idx >> 9, k = idx & 511;
    sWXP[idx] = (n < DTRANK + 2 * DSTATE) ? Wx[n * DINNER + k] : 0.f;
}
__global__ void pad_wf1_k(const float* __restrict__ Wf1)
{
    int idx = blockIdx.x * blockDim.x + threadIdx.x;
    int n = idx >> 8, k = idx & 255;
    sWF1P[idx] = (n < HMLP) ? Wf1[n * DMODEL + k] : 0.f;
}

// ---------------- depthwise causal conv + SiLU -> sU only ----------------
__global__ __launch_bounds__(256)
void conv_silu_k(const float* __restrict__ cw, const float* __restrict__ cb)
{
    int idx = blockIdx.x * blockDim.x + threadIdx.x;
    int e   = idx & (DINNER - 1);
    int bl  = idx >> 9;
    int l   = bl & (Ll - 1);

    float acc = cb[e];
    #pragma unroll
    for (int k = 0; k < DCONV; ++k) {
        int ll = l - (DCONV - 1) + k;
        if (ll >= 0)
            acc = fmaf(sXC[(size_t)(bl - (DCONV - 1) + k) * DINNER + e], cw[e * DCONV + k], acc);
    }
    float u = acc / (1.f + __expf(-acc));
    sU[idx] = u;
}

// ---------------- dt projection + softplus; writes full {dt,u} float2 ----------------
#define DT_ROWS 128
__global__ __launch_bounds__(512)
void dt_k(const float* __restrict__ Wdt, const float* __restrict__ bdt)
{
    const int d  = threadIdx.x;
    const int m0 = blockIdx.x * DT_ROWS;

    const float4* wp = (const float4*)(Wdt + d * DTRANK);
    const float4 w0 = wp[0], w1 = wp[1], w2 = wp[2], w3 = wp[3];
    const float  bb = bdt[d];

    __shared__ float lo[32 * DTRANK];

    for (int batch = 0; batch < DT_ROWS / 32; ++batch) {
        const int mb = m0 + batch * 32;
        __syncthreads();
        lo[d] = sDTLO[(size_t)mb * DTRANK + d];
        __syncthreads();

        #pragma unroll 4
        for (int r = 0; r < 32; ++r) {
            const float4* lp = (const float4*)&lo[r * DTRANK];
            float4 l0 = lp[0], l1 = lp[1], l2 = lp[2], l3 = lp[3];
            float acc = bb;
            acc = fmaf(l0.x, w0.x, acc); acc = fmaf(l0.y, w0.y, acc);
            acc = fmaf(l0.z, w0.z, acc); acc = fmaf(l0.w, w0.w, acc);
            acc = fmaf(l1.x, w1.x, acc); acc = fmaf(l1.y, w1.y, acc);
            acc = fmaf(l1.z, w1.z, acc); acc = fmaf(l1.w, w1.w, acc);
            acc = fmaf(l2.x, w2.x, acc); acc = fmaf(l2.y, w2.y, acc);
            acc = fmaf(l2.z, w2.z, acc); acc = fmaf(l2.w, w2.w, acc);
            acc = fmaf(l3.x, w3.x, acc); acc = fmaf(l3.y, w3.y, acc);
            acc = fmaf(l3.z, w3.z, acc); acc = fmaf(l3.w, w3.w, acc);

            float sp = (acc > 20.f) ? acc : log1pf(__expf(acc));
            float u  = sU[(size_t)(mb + r) * DINNER + d];
            sDU[(size_t)(mb + r) * DINNER + d] = make_float2(sp, u);
        }
    }
}

// ---------------- selective scan: 2 channels/warp, 2 states/lane ----------------
// lane = half*16 + j : channel d = blockIdx.x*8 + warp*2 + half, states {2j, 2j+1}
__global__ __launch_bounds__(128)
void scan_k(const float* __restrict__ A_log, const float* __restrict__ Dp)
{
    const int b    = blockIdx.y;
    const int warp = threadIdx.x >> 5;
    const int lane = threadIdx.x & 31;
    const int half = lane >> 4;
    const int j    = lane & 15;
    const int d    = blockIdx.x * 8 + warp * 2 + half;
    const int s0   = 2 * j;

    const float A2a = -__expf(A_log[d * DSTATE + s0])     * 1.4426950408889634f;
    const float A2b = -__expf(A_log[d * DSTATE + s0 + 1]) * 1.4426950408889634f;
    const float Dd  = Dp[d];

    const size_t row0 = (size_t)b * Ll;
    const float2* __restrict__ du = sDU + row0 * DINNER + d;
    const float4* __restrict__ bc = (const float4*)sBC + row0 * (DSTATE / 2) + j;
    const float*  __restrict__ zp = sZ  + row0 * DINNER + d;
    float*        __restrict__ yp = sY  + row0 * DINNER + d;

    float h0 = 0.f, h1 = 0.f;

    // prefetch iteration 0
    float2 duv = du[0];
    float4 bcv = bc[0];
    float  zv  = zp[0];

    for (int l = 0; l < Ll; ++l) {
        // prefetch next iteration (arrays padded +1 row; last read unused)
        float2 duv_n = du[(size_t)(l + 1) * DINNER];
        float4 bcv_n = bc[(size_t)(l + 1) * (DSTATE / 2)];
        float  zv_n  = zp[(size_t)(l + 1) * DINNER];

        float dtu = duv.x * duv.y;
        float e0  = fast_exp2(duv.x * A2a);
        float e1  = fast_exp2(duv.x * A2b);
        h0 = fmaf(h0, e0, dtu * bcv.x);
        h1 = fmaf(h1, e1, dtu * bcv.z);
        float y = fmaf(h1, bcv.w, h0 * bcv.y);

        // 16-lane butterfly (stays within each half-warp)
        y += __shfl_xor_sync(0xffffffffu, y, 8);
        y += __shfl_xor_sync(0xffffffffu, y, 4);
        y += __shfl_xor_sync(0xffffffffu, y, 2);
        y += __shfl_xor_sync(0xffffffffu, y, 1);

        if (j == 0) {
            y = fmaf(duv.y, Dd, y);
            float t  = fast_exp2(-1.4426950408889634f * zv);
            float g  = __fdividef(zv, 1.f + t);     // silu(z)
            yp[(size_t)l * DINNER] = y * g;
        }

        duv = duv_n; bcv = bcv_n; zv = zv_n;
    }
}

// ---------------- launch ----------------
extern "C" void kernel_launch(void* const* d_in, const int* in_sizes, int n_in,
                              void* d_out, int out_size)
{
    const float* x      = (const float*)d_in[0];
    const float* W_in   = (const float*)d_in[1];
    const float* conv_w = (const float*)d_in[2];
    const float* conv_b = (const float*)d_in[3];
    const float* W_xprj = (const float*)d_in[4];
    const float* W_dt   = (const float*)d_in[5];
    const float* b_dt   = (const float*)d_in[6];
    const float* A_log  = (const float*)d_in[7];
    const float* Dvec   = (const float*)d_in[8];
    const float* W_out  = (const float*)d_in[9];
    const float* W_ff1  = (const float*)d_in[10];
    const float* b_ff1  = (const float*)d_in[11];
    const float* W_ff2  = (const float*)d_in[12];
    const float* b_ff2  = (const float*)d_in[13];
    float* out = (float*)d_out;

    float *pXC, *pZ, *pU, *pDTLO, *pY, *pM, *pH, *pWXP, *pWF1P;
    float2 *pDU, *pBC;
    cudaGetSymbolAddress((void**)&pXC,   sXC);
    cudaGetSymbolAddress((void**)&pZ,    sZ);
    cudaGetSymbolAddress((void**)&pU,    sU);
    cudaGetSymbolAddress((void**)&pDU,   sDU);
    cudaGetSymbolAddress((void**)&pDTLO, sDTLO);
    cudaGetSymbolAddress((void**)&pBC,   sBC);
    cudaGetSymbolAddress((void**)&pY,    sY);
    cudaGetSymbolAddress((void**)&pM,    sM);
    cudaGetSymbolAddress((void**)&pH,    sH);
    cudaGetSymbolAddress((void**)&pWXP,  sWXP);
    cudaGetSymbolAddress((void**)&pWF1P, sWF1P);

    // 0) pad small weights
    pad_wx_k <<<(128 * DINNER) / 256, 256>>>(W_xprj);
    pad_wf1_k<<<(128 * DMODEL) / 256, 256>>>(W_ff1);

    // 1) xz = x @ W_in^T -> xc/z
    {
        dim3 g((2 * DINNER) / TBN, ML / TBM);
        tgemm_k<EPI_SPLITXZ><<<g, 256>>>(x, W_in, nullptr, nullptr,
                                         ML, 2 * DINNER, DMODEL, 2 * DINNER, pXC, pZ);
    }
    // 2) conv + silu -> u
    conv_silu_k<<<(ML * DINNER) / 256, 256>>>(conv_w, conv_b);

    // 3) dbc = u @ Wxproj^T -> dtlo / {B,C}
    {
        dim3 g(1, ML / TBM);
        tgemm_k<EPI_DBC><<<g, 256>>>(pU, pWXP, nullptr, pDTLO,
                                     ML, 128, DINNER, DTRANK + 2 * DSTATE, (float*)pBC, nullptr);
    }
    // 4) dt = softplus(dtlo @ W_dt^T + b_dt); writes {dt,u}
    dt_k<<<ML / DT_ROWS, DINNER>>>(W_dt, b_dt);

    // 5) selective scan
    {
        dim3 g(DINNER / 8, Bb);
        scan_k<<<g, 128>>>(A_log, Dvec);
    }
    // 6) m = y @ W_out^T
    {
        dim3 g(DMODEL / TBN, ML / TBM);
        tgemm_k<EPI_PLAIN><<<g, 256>>>(pY, W_out, nullptr, pM,
                                       ML, DMODEL, DINNER, DMODEL, nullptr, nullptr);
    }
    // 7) h = leaky_relu(m @ W_ff1^T + b_ff1)
    {
        dim3 g(1, ML / TBM);
        tgemm_k<EPI_LEAKY><<<g, 256>>>(pM, pWF1P, b_ff1, pH,
                                       ML, 128, DMODEL, HMLP, nullptr, nullptr);
    }
    // 8) out = sigmoid(h @ W_ff2^T + b_ff2)
    {
        dim3 g(BINS / TBN, ML / TBM);
        tgemm_k<EPI_SIGMOID><<<g, 256>>>(pH, W_ff2, b_ff2, out,
                                         ML, BINS, HMLP, BINS, nullptr, nullptr);
    }
}

// round 7
// speedup vs baseline: 2.2595x; 1.0277x over previous
#include <cuda_runtime.h>
#include <cstdint>

// ---------------- problem constants ----------------
#define Bb      16
#define Ll      2048
#define DMODEL  256
#define DINNER  512
#define DSTATE  32
#define DCONV   4
#define DTRANK  16
#define HMLP    32
#define BINS    256
#define ML      (Bb*Ll)            // 32768 rows

__device__ __forceinline__ float fast_exp2(float x) {
    float r;
    asm("ex2.approx.ftz.f32 %0, %1;" : "=f"(r) : "f"(x));
    return r;
}
__device__ __forceinline__ void cp_async16(uint32_t smem_addr, const void* gptr) {
    asm volatile("cp.async.cg.shared.global [%0], [%1], 16;\n"
                 :: "r"(smem_addr), "l"(gptr));
}
__device__ __forceinline__ void cp_commit() {
    asm volatile("cp.async.commit_group;\n");
}
template<int N>
__device__ __forceinline__ void cp_wait() {
    asm volatile("cp.async.wait_group %0;\n" :: "n"(N));
}

// ---------------- scratch (static device arrays; no allocation) ----------------
__device__ float  sXC  [(size_t)ML * DINNER];
__device__ float  sZ   [(size_t)(ML + 1) * DINNER];
__device__ float  sU   [(size_t)ML * DINNER];
__device__ float2 sDU  [(size_t)(ML + 1) * DINNER];  // {dt, u}
__device__ float  sDTLO[(size_t)ML * DTRANK];
__device__ float2 sBC  [(size_t)(ML + 1) * DSTATE];  // {B, C} interleaved
__device__ float  sY   [(size_t)ML * DINNER];
__device__ float  sM   [(size_t)ML * DMODEL];
__device__ float  sH   [(size_t)ML * HMLP];
__device__ float  sWXP [128 * DINNER];
__device__ float  sWF1P[128 * DMODEL];

// epilogue modes
#define EPI_PLAIN   0
#define EPI_SPLITXZ 1
#define EPI_DBC     2
#define EPI_LEAKY   3
#define EPI_SIGMOID 4

// ---------------- tf32 tensor-core GEMM, cp.async double-buffered ----------------
#define TBM 128
#define TBN 128
#define TBK 32
#define SSTR 36   // row stride in words; row pitch 144B = 16B-aligned, conflict-free frags

template<int E>
__global__ __launch_bounds__(256, 2)
void tgemm_k(const float* __restrict__ A, const float* __restrict__ W,
             const float* __restrict__ bias, float* __restrict__ C,
             int M, int N, int K, int realN,
             float* __restrict__ aux0, float* __restrict__ aux1)
{
    __shared__ uint32_t As[2][TBM][SSTR];   // raw fp32 bits; mma.tf32 truncates
    __shared__ uint32_t Ws[2][TBN][SSTR];

    const int tid  = threadIdx.x;
    const int lane = tid & 31;
    const int wid  = tid >> 5;
    const int wm   = wid & 1;
    const int wn   = wid >> 1;
    const int m0   = blockIdx.y * TBM;
    const int n0   = blockIdx.x * TBN;
    const int g    = lane >> 2;
    const int t    = lane & 3;

    const uint32_t aBase = (uint32_t)__cvta_generic_to_shared(&As[0][0][0]);
    const uint32_t wBase = (uint32_t)__cvta_generic_to_shared(&Ws[0][0][0]);
    const int lrow = tid >> 3;          // 0..31 (+32r)
    const int lkq  = tid & 7;           // 16B chunk within row

    float acc[4][4][4];
    #pragma unroll
    for (int i = 0; i < 4; ++i)
        #pragma unroll
        for (int j = 0; j < 4; ++j)
            #pragma unroll
            for (int q = 0; q < 4; ++q) acc[i][j][q] = 0.f;

    const int nk = K / TBK;

#define ISSUE_TILE(buf, kk0)                                                        \
    {                                                                               \
        _Pragma("unroll")                                                           \
        for (int r = 0; r < 4; ++r) {                                               \
            int row = lrow + 32 * r;                                                \
            cp_async16(aBase + (uint32_t)(((buf) * TBM + row) * SSTR + lkq * 4) * 4,\
                       A + (size_t)(m0 + row) * K + (kk0) + lkq * 4);               \
        }                                                                           \
        _Pragma("unroll")                                                           \
        for (int r = 0; r < 4; ++r) {                                               \
            int row = lrow + 32 * r;                                                \
            cp_async16(wBase + (uint32_t)(((buf) * TBN + row) * SSTR + lkq * 4) * 4,\
                       W + (size_t)(n0 + row) * K + (kk0) + lkq * 4);               \
        }                                                                           \
        cp_commit();                                                                \
    }

    ISSUE_TILE(0, 0);

    int buf = 0;
    for (int it = 0; it < nk; ++it) {
        if (it + 1 < nk) {
            ISSUE_TILE(buf ^ 1, (it + 1) * TBK);
            cp_wait<1>();
        } else {
            cp_wait<0>();
        }
        __syncthreads();

        #pragma unroll
        for (int k8 = 0; k8 < 4; ++k8) {
            const int kc = k8 * 8 + t;
            uint32_t a[4][4];
            #pragma unroll
            for (int mf = 0; mf < 4; ++mf) {
                const int r0 = wm * 64 + mf * 16 + g;
                a[mf][0] = As[buf][r0    ][kc];
                a[mf][1] = As[buf][r0 + 8][kc];
                a[mf][2] = As[buf][r0    ][kc + 4];
                a[mf][3] = As[buf][r0 + 8][kc + 4];
            }
            uint32_t b[4][2];
            #pragma unroll
            for (int nf = 0; nf < 4; ++nf) {
                const int rb = wn * 32 + nf * 8 + g;
                b[nf][0] = Ws[buf][rb][kc];
                b[nf][1] = Ws[buf][rb][kc + 4];
            }
            #pragma unroll
            for (int mf = 0; mf < 4; ++mf)
                #pragma unroll
                for (int nf = 0; nf < 4; ++nf) {
                    float* d = acc[mf][nf];
                    asm volatile(
                        "mma.sync.aligned.m16n8k8.row.col.f32.tf32.tf32.f32 "
                        "{%0,%1,%2,%3}, {%4,%5,%6,%7}, {%8,%9}, {%0,%1,%2,%3};\n"
                        : "+f"(d[0]), "+f"(d[1]), "+f"(d[2]), "+f"(d[3])
                        : "r"(a[mf][0]), "r"(a[mf][1]), "r"(a[mf][2]), "r"(a[mf][3]),
                          "r"(b[nf][0]), "r"(b[nf][1]));
                }
        }
        __syncthreads();
        buf ^= 1;
    }
#undef ISSUE_TILE

    // epilogue (paired 8B stores; all split points are even)
    #pragma unroll
    for (int mf = 0; mf < 4; ++mf) {
        const int rowb = m0 + wm * 64 + mf * 16 + g;
        #pragma unroll
        for (int nf = 0; nf < 4; ++nf) {
            const int colb = n0 + wn * 32 + nf * 8 + 2 * t;
            #pragma unroll
            for (int half = 0; half < 2; ++half) {
                const int m = rowb + half * 8;
                float v0 = acc[mf][nf][half * 2 + 0];
                float v1 = acc[mf][nf][half * 2 + 1];
                if (E == EPI_PLAIN) {
                    *(float2*)&C[(size_t)m * N + colb] = make_float2(v0, v1);
                } else if (E == EPI_SPLITXZ) {
                    if (colb < DINNER)
                        *(float2*)&aux0[(size_t)m * DINNER + colb] = make_float2(v0, v1);
                    else
                        *(float2*)&aux1[(size_t)m * DINNER + (colb - DINNER)] = make_float2(v0, v1);
                } else if (E == EPI_DBC) {
                    #pragma unroll
                    for (int q = 0; q < 2; ++q) {
                        const int col = colb + q;
                        float v = q ? v1 : v0;
                        if (col < DTRANK)
                            C[(size_t)m * DTRANK + col] = v;
                        else if (col < DTRANK + DSTATE)
                            aux0[((size_t)m * DSTATE + (col - DTRANK)) * 2 + 0] = v;
                        else if (col < DTRANK + 2 * DSTATE)
                            aux0[((size_t)m * DSTATE + (col - DTRANK - DSTATE)) * 2 + 1] = v;
                    }
                } else if (E == EPI_LEAKY) {
                    if (colb + 1 < realN) {
                        v0 += bias[colb];     v0 = (v0 > 0.f) ? v0 : 0.01f * v0;
                        v1 += bias[colb + 1]; v1 = (v1 > 0.f) ? v1 : 0.01f * v1;
                        *(float2*)&C[(size_t)m * realN + colb] = make_float2(v0, v1);
                    }
                } else if (E == EPI_SIGMOID) {
                    v0 += bias[colb];     v0 = 1.f / (1.f + __expf(-v0));
                    v1 += bias[colb + 1]; v1 = 1.f / (1.f + __expf(-v1));
                    *(float2*)&C[(size_t)m * N + colb] = make_float2(v0, v1);
                }
            }
        }
    }
}

// ---------------- weight pad kernels ----------------
__global__ void pad_wx_k(const float* __restrict__ Wx)
{
    int idx = blockIdx.x * blockDim.x + threadIdx.x;
    int n = idx >> 9, k = idx & 511;
    sWXP[idx] = (n < DTRANK + 2 * DSTATE) ? Wx[n * DINNER + k] : 0.f;
}
__global__ void pad_wf1_k(const float* __restrict__ Wf1)
{
    int idx = blockIdx.x * blockDim.x + threadIdx.x;
    int n = idx >> 8, k = idx & 255;
    sWF1P[idx] = (n < HMLP) ? Wf1[n * DMODEL + k] : 0.f;
}

// ---------------- depthwise causal conv + SiLU -> sU ----------------
__global__ __launch_bounds__(256)
void conv_silu_k(const float* __restrict__ cw, const float* __restrict__ cb)
{
    int idx = blockIdx.x * blockDim.x + threadIdx.x;
    int e   = idx & (DINNER - 1);
    int bl  = idx >> 9;
    int l   = bl & (Ll - 1);

    float acc = cb[e];
    #pragma unroll
    for (int k = 0; k < DCONV; ++k) {
        int ll = l - (DCONV - 1) + k;
        if (ll >= 0)
            acc = fmaf(sXC[(size_t)(bl - (DCONV - 1) + k) * DINNER + e], cw[e * DCONV + k], acc);
    }
    float u = acc / (1.f + __expf(-acc));
    sU[idx] = u;
}

// ---------------- dt projection + softplus; writes full {dt,u} float2 ----------------
#define DT_ROWS 128
__global__ __launch_bounds__(512)
void dt_k(const float* __restrict__ Wdt, const float* __restrict__ bdt)
{
    const int d  = threadIdx.x;
    const int m0 = blockIdx.x * DT_ROWS;

    const float4* wp = (const float4*)(Wdt + d * DTRANK);
    const float4 w0 = wp[0], w1 = wp[1], w2 = wp[2], w3 = wp[3];
    const float  bb = bdt[d];

    __shared__ float lo[32 * DTRANK];

    for (int batch = 0; batch < DT_ROWS / 32; ++batch) {
        const int mb = m0 + batch * 32;
        __syncthreads();
        lo[d] = sDTLO[(size_t)mb * DTRANK + d];
        __syncthreads();

        #pragma unroll 4
        for (int r = 0; r < 32; ++r) {
            const float4* lp = (const float4*)&lo[r * DTRANK];
            float4 l0 = lp[0], l1 = lp[1], l2 = lp[2], l3 = lp[3];
            float acc = bb;
            acc = fmaf(l0.x, w0.x, acc); acc = fmaf(l0.y, w0.y, acc);
            acc = fmaf(l0.z, w0.z, acc); acc = fmaf(l0.w, w0.w, acc);
            acc = fmaf(l1.x, w1.x, acc); acc = fmaf(l1.y, w1.y, acc);
            acc = fmaf(l1.z, w1.z, acc); acc = fmaf(l1.w, w1.w, acc);
            acc = fmaf(l2.x, w2.x, acc); acc = fmaf(l2.y, w2.y, acc);
            acc = fmaf(l2.z, w2.z, acc); acc = fmaf(l2.w, w2.w, acc);
            acc = fmaf(l3.x, w3.x, acc); acc = fmaf(l3.y, w3.y, acc);
            acc = fmaf(l3.z, w3.z, acc); acc = fmaf(l3.w, w3.w, acc);

            float sp = (acc > 20.f) ? acc : log1pf(__expf(acc));
            float u  = sU[(size_t)(mb + r) * DINNER + d];
            sDU[(size_t)(mb + r) * DINNER + d] = make_float2(sp, u);
        }
    }
}

// ---------------- selective scan: 2 channels/warp, 2 states/lane ----------------
__global__ __launch_bounds__(128)
void scan_k(const float* __restrict__ A_log, const float* __restrict__ Dp)
{
    const int b    = blockIdx.y;
    const int warp = threadIdx.x >> 5;
    const int lane = threadIdx.x & 31;
    const int half = lane >> 4;
    const int j    = lane & 15;
    const int d    = blockIdx.x * 8 + warp * 2 + half;
    const int s0   = 2 * j;

    const float A2a = -__expf(A_log[d * DSTATE + s0])     * 1.4426950408889634f;
    const float A2b = -__expf(A_log[d * DSTATE + s0 + 1]) * 1.4426950408889634f;
    const float Dd  = Dp[d];

    const size_t row0 = (size_t)b * Ll;
    const float2* __restrict__ du = sDU + row0 * DINNER + d;
    const float4* __restrict__ bc = (const float4*)sBC + row0 * (DSTATE / 2) + j;
    const float*  __restrict__ zp = sZ  + row0 * DINNER + d;
    float*        __restrict__ yp = sY  + row0 * DINNER + d;

    float h0 = 0.f, h1 = 0.f;

    float2 duv = du[0];
    float4 bcv = bc[0];
    float  zv  = zp[0];

    for (int l = 0; l < Ll; ++l) {
        float2 duv_n = du[(size_t)(l + 1) * DINNER];
        float4 bcv_n = bc[(size_t)(l + 1) * (DSTATE / 2)];
        float  zv_n  = zp[(size_t)(l + 1) * DINNER];

        float dtu = duv.x * duv.y;
        float e0  = fast_exp2(duv.x * A2a);
        float e1  = fast_exp2(duv.x * A2b);
        h0 = fmaf(h0, e0, dtu * bcv.x);
        h1 = fmaf(h1, e1, dtu * bcv.z);
        float y = fmaf(h1, bcv.w, h0 * bcv.y);

        y += __shfl_xor_sync(0xffffffffu, y, 8);
        y += __shfl_xor_sync(0xffffffffu, y, 4);
        y += __shfl_xor_sync(0xffffffffu, y, 2);
        y += __shfl_xor_sync(0xffffffffu, y, 1);

        if (j == 0) {
            y = fmaf(duv.y, Dd, y);
            float t  = fast_exp2(-1.4426950408889634f * zv);
            float g  = __fdividef(zv, 1.f + t);
            yp[(size_t)l * DINNER] = y * g;
        }

        duv = duv_n; bcv = bcv_n; zv = zv_n;
    }
}

// ---------------- launch ----------------
extern "C" void kernel_launch(void* const* d_in, const int* in_sizes, int n_in,
                              void* d_out, int out_size)
{
    const float* x      = (const float*)d_in[0];
    const float* W_in   = (const float*)d_in[1];
    const float* conv_w = (const float*)d_in[2];
    const float* conv_b = (const float*)d_in[3];
    const float* W_xprj = (const float*)d_in[4];
    const float* W_dt   = (const float*)d_in[5];
    const float* b_dt   = (const float*)d_in[6];
    const float* A_log  = (const float*)d_in[7];
    const float* Dvec   = (const float*)d_in[8];
    const float* W_out  = (const float*)d_in[9];
    const float* W_ff1  = (const float*)d_in[10];
    const float* b_ff1  = (const float*)d_in[11];
    const float* W_ff2  = (const float*)d_in[12];
    const float* b_ff2  = (const float*)d_in[13];
    float* out = (float*)d_out;

    float *pXC, *pZ, *pU, *pDTLO, *pY, *pM, *pH, *pWXP, *pWF1P;
    float2 *pDU, *pBC;
    cudaGetSymbolAddress((void**)&pXC,   sXC);
    cudaGetSymbolAddress((void**)&pZ,    sZ);
    cudaGetSymbolAddress((void**)&pU,    sU);
    cudaGetSymbolAddress((void**)&pDU,   sDU);
    cudaGetSymbolAddress((void**)&pDTLO, sDTLO);
    cudaGetSymbolAddress((void**)&pBC,   sBC);
    cudaGetSymbolAddress((void**)&pY,    sY);
    cudaGetSymbolAddress((void**)&pM,    sM);
    cudaGetSymbolAddress((void**)&pH,    sH);
    cudaGetSymbolAddress((void**)&pWXP,  sWXP);
    cudaGetSymbolAddress((void**)&pWF1P, sWF1P);

    // 0) pad small weights
    pad_wx_k <<<(128 * DINNER) / 256, 256>>>(W_xprj);
    pad_wf1_k<<<(128 * DMODEL) / 256, 256>>>(W_ff1);

    // 1) xz = x @ W_in^T -> xc/z
    {
        dim3 g((2 * DINNER) / TBN, ML / TBM);
        tgemm_k<EPI_SPLITXZ><<<g, 256>>>(x, W_in, nullptr, nullptr,
                                         ML, 2 * DINNER, DMODEL, 2 * DINNER, pXC, pZ);
    }
    // 2) conv + silu -> u
    conv_silu_k<<<(ML * DINNER) / 256, 256>>>(conv_w, conv_b);

    // 3) dbc = u @ Wxproj^T -> dtlo / {B,C}
    {
        dim3 g(1, ML / TBM);
        tgemm_k<EPI_DBC><<<g, 256>>>(pU, pWXP, nullptr, pDTLO,
                                     ML, 128, DINNER, DTRANK + 2 * DSTATE, (float*)pBC, nullptr);
    }
    // 4) dt = softplus(dtlo @ W_dt^T + b_dt); writes {dt,u}
    dt_k<<<ML / DT_ROWS, DINNER>>>(W_dt, b_dt);

    // 5) selective scan
    {
        dim3 g(DINNER / 8, Bb);
        scan_k<<<g, 128>>>(A_log, Dvec);
    }
    // 6) m = y @ W_out^T
    {
        dim3 g(DMODEL / TBN, ML / TBM);
        tgemm_k<EPI_PLAIN><<<g, 256>>>(pY, W_out, nullptr, pM,
                                       ML, DMODEL, DINNER, DMODEL, nullptr, nullptr);
    }
    // 7) h = leaky_relu(m @ W_ff1^T + b_ff1)
    {
        dim3 g(1, ML / TBM);
        tgemm_k<EPI_LEAKY><<<g, 256>>>(pM, pWF1P, b_ff1, pH,
                                       ML, 128, DMODEL, HMLP, nullptr, nullptr);
    }
    // 8) out = sigmoid(h @ W_ff2^T + b_ff2)
    {
        dim3 g(BINS / TBN, ML / TBM);
        tgemm_k<EPI_SIGMOID><<<g, 256>>>(pH, W_ff2, b_ff2, out,
                                         ML, BINS, HMLP, BINS, nullptr, nullptr);
    }
}

// round 8
// speedup vs baseline: 4.4728x; 1.9796x over previous
#include <cuda_runtime.h>
#include <cstdint>

// ---------------- problem constants ----------------
#define Bb      16
#define Ll      2048
#define DMODEL  256
#define DINNER  512
#define DSTATE  32
#define DCONV   4
#define DTRANK  16
#define HMLP    32
#define BINS    256
#define ML      (Bb*Ll)            // 32768 rows

__device__ __forceinline__ float fast_exp2(float x) {
    float r;
    asm("ex2.approx.ftz.f32 %0, %1;" : "=f"(r) : "f"(x));
    return r;
}
__device__ __forceinline__ void cp_async16(uint32_t smem_addr, const void* gptr) {
    asm volatile("cp.async.cg.shared.global [%0], [%1], 16;\n"
                 :: "r"(smem_addr), "l"(gptr));
}
__device__ __forceinline__ void cp_commit() {
    asm volatile("cp.async.commit_group;\n");
}
template<int N>
__device__ __forceinline__ void cp_wait() {
    asm volatile("cp.async.wait_group %0;\n" :: "n"(N));
}

// ---------------- scratch ----------------
__device__ float  sXC  [(size_t)ML * DINNER];
__device__ float  sZ   [(size_t)(ML + 1) * DINNER];
__device__ float  sU   [(size_t)ML * DINNER];
__device__ float2 sDU  [(size_t)(ML + 1) * DINNER];  // {dt, u}
__device__ float  sDTLO[(size_t)ML * DTRANK];
__device__ float2 sBC  [(size_t)(ML + 1) * DSTATE];  // {B, C} interleaved
__device__ float  sY   [(size_t)ML * DINNER];
__device__ float  sM   [(size_t)ML * DMODEL];
__device__ float  sH   [(size_t)ML * HMLP];
__device__ float  sWXP [128 * DINNER];
__device__ float  sWF1P[128 * DMODEL];

// epilogue modes
#define EPI_PLAIN   0
#define EPI_SPLITXZ 1
#define EPI_DBC     2
#define EPI_LEAKY   3
#define EPI_SIGMOID 4

// ---------------- tf32 tensor-core GEMM, cp.async double-buffered ----------------
#define TBM 128
#define TBN 128
#define TBK 32
#define SSTR 36

template<int E>
__global__ __launch_bounds__(256, 2)
void tgemm_k(const float* __restrict__ A, const float* __restrict__ W,
             const float* __restrict__ bias, float* __restrict__ C,
             int M, int N, int K, int realN,
             float* __restrict__ aux0, float* __restrict__ aux1)
{
    __shared__ uint32_t As[2][TBM][SSTR];
    __shared__ uint32_t Ws[2][TBN][SSTR];

    const int tid  = threadIdx.x;
    const int lane = tid & 31;
    const int wid  = tid >> 5;
    const int wm   = wid & 1;
    const int wn   = wid >> 1;
    const int m0   = blockIdx.y * TBM;
    const int n0   = blockIdx.x * TBN;
    const int g    = lane >> 2;
    const int t    = lane & 3;

    const uint32_t aBase = (uint32_t)__cvta_generic_to_shared(&As[0][0][0]);
    const uint32_t wBase = (uint32_t)__cvta_generic_to_shared(&Ws[0][0][0]);
    const int lrow = tid >> 3;
    const int lkq  = tid & 7;

    float acc[4][4][4];
    #pragma unroll
    for (int i = 0; i < 4; ++i)
        #pragma unroll
        for (int j = 0; j < 4; ++j)
            #pragma unroll
            for (int q = 0; q < 4; ++q) acc[i][j][q] = 0.f;

    const int nk = K / TBK;

#define ISSUE_TILE(buf, kk0)                                                        \
    {                                                                               \
        _Pragma("unroll")                                                           \
        for (int r = 0; r < 4; ++r) {                                               \
            int row = lrow + 32 * r;                                                \
            cp_async16(aBase + (uint32_t)(((buf) * TBM + row) * SSTR + lkq * 4) * 4,\
                       A + (size_t)(m0 + row) * K + (kk0) + lkq * 4);               \
        }                                                                           \
        _Pragma("unroll")                                                           \
        for (int r = 0; r < 4; ++r) {                                               \
            int row = lrow + 32 * r;                                                \
            cp_async16(wBase + (uint32_t)(((buf) * TBN + row) * SSTR + lkq * 4) * 4,\
                       W + (size_t)(n0 + row) * K + (kk0) + lkq * 4);               \
        }                                                                           \
        cp_commit();                                                                \
    }

    ISSUE_TILE(0, 0);

    int buf = 0;
    for (int it = 0; it < nk; ++it) {
        if (it + 1 < nk) {
            ISSUE_TILE(buf ^ 1, (it + 1) * TBK);
            cp_wait<1>();
        } else {
            cp_wait<0>();
        }
        __syncthreads();

        #pragma unroll
        for (int k8 = 0; k8 < 4; ++k8) {
            const int kc = k8 * 8 + t;
            uint32_t a[4][4];
            #pragma unroll
            for (int mf = 0; mf < 4; ++mf) {
                const int r0 = wm * 64 + mf * 16 + g;
                a[mf][0] = As[buf][r0    ][kc];
                a[mf][1] = As[buf][r0 + 8][kc];
                a[mf][2] = As[buf][r0    ][kc + 4];
                a[mf][3] = As[buf][r0 + 8][kc + 4];
            }
            uint32_t b[4][2];
            #pragma unroll
            for (int nf = 0; nf < 4; ++nf) {
                const int rb = wn * 32 + nf * 8 + g;
                b[nf][0] = Ws[buf][rb][kc];
                b[nf][1] = Ws[buf][rb][kc + 4];
            }
            #pragma unroll
            for (int mf = 0; mf < 4; ++mf)
                #pragma unroll
                for (int nf = 0; nf < 4; ++nf) {
                    float* d = acc[mf][nf];
                    asm volatile(
                        "mma.sync.aligned.m16n8k8.row.col.f32.tf32.tf32.f32 "
                        "{%0,%1,%2,%3}, {%4,%5,%6,%7}, {%8,%9}, {%0,%1,%2,%3};\n"
                        : "+f"(d[0]), "+f"(d[1]), "+f"(d[2]), "+f"(d[3])
                        : "r"(a[mf][0]), "r"(a[mf][1]), "r"(a[mf][2]), "r"(a[mf][3]),
                          "r"(b[nf][0]), "r"(b[nf][1]));
                }
        }
        __syncthreads();
        buf ^= 1;
    }
#undef ISSUE_TILE

    #pragma unroll
    for (int mf = 0; mf < 4; ++mf) {
        const int rowb = m0 + wm * 64 + mf * 16 + g;
        #pragma unroll
        for (int nf = 0; nf < 4; ++nf) {
            const int colb = n0 + wn * 32 + nf * 8 + 2 * t;
            #pragma unroll
            for (int half = 0; half < 2; ++half) {
                const int m = rowb + half * 8;
                float v0 = acc[mf][nf][half * 2 + 0];
                float v1 = acc[mf][nf][half * 2 + 1];
                if (E == EPI_PLAIN) {
                    *(float2*)&C[(size_t)m * N + colb] = make_float2(v0, v1);
                } else if (E == EPI_SPLITXZ) {
                    if (colb < DINNER)
                        *(float2*)&aux0[(size_t)m * DINNER + colb] = make_float2(v0, v1);
                    else
                        *(float2*)&aux1[(size_t)m * DINNER + (colb - DINNER)] = make_float2(v0, v1);
                } else if (E == EPI_DBC) {
                    #pragma unroll
                    for (int q = 0; q < 2; ++q) {
                        const int col = colb + q;
                        float v = q ? v1 : v0;
                        if (col < DTRANK)
                            C[(size_t)m * DTRANK + col] = v;
                        else if (col < DTRANK + DSTATE)
                            aux0[((size_t)m * DSTATE + (col - DTRANK)) * 2 + 0] = v;
                        else if (col < DTRANK + 2 * DSTATE)
                            aux0[((size_t)m * DSTATE + (col - DTRANK - DSTATE)) * 2 + 1] = v;
                    }
                } else if (E == EPI_LEAKY) {
                    if (colb + 1 < realN) {
                        v0 += bias[colb];     v0 = (v0 > 0.f) ? v0 : 0.01f * v0;
                        v1 += bias[colb + 1]; v1 = (v1 > 0.f) ? v1 : 0.01f * v1;
                        *(float2*)&C[(size_t)m * realN + colb] = make_float2(v0, v1);
                    }
                } else if (E == EPI_SIGMOID) {
                    v0 += bias[colb];     v0 = 1.f / (1.f + __expf(-v0));
                    v1 += bias[colb + 1]; v1 = 1.f / (1.f + __expf(-v1));
                    *(float2*)&C[(size_t)m * N + colb] = make_float2(v0, v1);
                }
            }
        }
    }
}

// ---------------- weight pad kernels ----------------
__global__ void pad_wx_k(const float* __restrict__ Wx)
{
    int idx = blockIdx.x * blockDim.x + threadIdx.x;
    int n = idx >> 9, k = idx & 511;
    sWXP[idx] = (n < DTRANK + 2 * DSTATE) ? Wx[n * DINNER + k] : 0.f;
}
__global__ void pad_wf1_k(const float* __restrict__ Wf1)
{
    int idx = blockIdx.x * blockDim.x + threadIdx.x;
    int n = idx >> 8, k = idx & 255;
    sWF1P[idx] = (n < HMLP) ? Wf1[n * DMODEL + k] : 0.f;
}

// ---------------- depthwise causal conv + SiLU (4 outputs per thread) ----------------
__global__ __launch_bounds__(256)
void conv_silu_k(const float* __restrict__ cw, const float* __restrict__ cb)
{
    int idx = blockIdx.x * blockDim.x + threadIdx.x;    // < ML*DINNER/4
    int e   = idx & (DINNER - 1);
    int lg  = idx >> 9;                                  // l-group
    int l0  = (lg & (Ll / 4 - 1)) * 4;
    size_t base = ((size_t)lg << 2) << 9;                // (lg*4)*512 row base

    float w0 = cw[e * DCONV + 0], w1 = cw[e * DCONV + 1];
    float w2 = cw[e * DCONV + 2], w3 = cw[e * DCONV + 3];
    float bbv = cb[e];

    // rows l0-3 .. l0+3 of xc for channel e
    float xm3 = (l0 >= 3) ? sXC[base - (size_t)3 * DINNER + e] : 0.f;
    float xm2 = (l0 >= 2) ? sXC[base - (size_t)2 * DINNER + e] : 0.f;
    float xm1 = (l0 >= 1) ? sXC[base - (size_t)1 * DINNER + e] : 0.f;
    float x0  = sXC[base + e];
    float x1  = sXC[base + (size_t)1 * DINNER + e];
    float x2  = sXC[base + (size_t)2 * DINNER + e];
    float x3  = sXC[base + (size_t)3 * DINNER + e];

    #pragma unroll
    for (int r = 0; r < 4; ++r) {
        float a = (r == 0) ? xm3 : (r == 1) ? xm2 : (r == 2) ? xm1 : x0;
        float b = (r == 0) ? xm2 : (r == 1) ? xm1 : (r == 2) ? x0  : x1;
        float c = (r == 0) ? xm1 : (r == 1) ? x0  : (r == 2) ? x1  : x2;
        float d = (r == 0) ? x0  : (r == 1) ? x1  : (r == 2) ? x2  : x3;
        float acc = bbv;
        acc = fmaf(a, w0, acc);
        acc = fmaf(b, w1, acc);
        acc = fmaf(c, w2, acc);
        acc = fmaf(d, w3, acc);
        float u = acc / (1.f + __expf(-acc));
        sU[base + (size_t)r * DINNER + e] = u;
    }
}

// ---------------- dt projection + softplus; writes full {dt,u} float2 ----------------
#define DT_ROWS 128
__global__ __launch_bounds__(512)
void dt_k(const float* __restrict__ Wdt, const float* __restrict__ bdt)
{
    const int d  = threadIdx.x;
    const int m0 = blockIdx.x * DT_ROWS;

    const float4* wp = (const float4*)(Wdt + d * DTRANK);
    const float4 w0 = wp[0], w1 = wp[1], w2 = wp[2], w3 = wp[3];
    const float  bb = bdt[d];

    __shared__ float lo[32 * DTRANK];

    for (int batch = 0; batch < DT_ROWS / 32; ++batch) {
        const int mb = m0 + batch * 32;
        __syncthreads();
        lo[d] = sDTLO[(size_t)mb * DTRANK + d];
        __syncthreads();

        #pragma unroll 4
        for (int r = 0; r < 32; ++r) {
            const float4* lp = (const float4*)&lo[r * DTRANK];
            float4 l0 = lp[0], l1 = lp[1], l2 = lp[2], l3 = lp[3];
            float acc = bb;
            acc = fmaf(l0.x, w0.x, acc); acc = fmaf(l0.y, w0.y, acc);
            acc = fmaf(l0.z, w0.z, acc); acc = fmaf(l0.w, w0.w, acc);
            acc = fmaf(l1.x, w1.x, acc); acc = fmaf(l1.y, w1.y, acc);
            acc = fmaf(l1.z, w1.z, acc); acc = fmaf(l1.w, w1.w, acc);
            acc = fmaf(l2.x, w2.x, acc); acc = fmaf(l2.y, w2.y, acc);
            acc = fmaf(l2.z, w2.z, acc); acc = fmaf(l2.w, w2.w, acc);
            acc = fmaf(l3.x, w3.x, acc); acc = fmaf(l3.y, w3.y, acc);
            acc = fmaf(l3.z, w3.z, acc); acc = fmaf(l3.w, w3.w, acc);

            float sp = (acc > 20.f) ? acc : log1pf(__expf(acc));
            float u  = sU[(size_t)(mb + r) * DINNER + d];
            sDU[(size_t)(mb + r) * DINNER + d] = make_float2(sp, u);
        }
    }
}

// ---------------- selective scan v3: smem-staged cp.async pipeline ----------------
// block = 128 thr = 4 warps = 32 channels; lane: channel = (wid*8 + (lane>>2)), q = lane&3
// states per lane: 8q .. 8q+7. Tiles of T=32 timesteps, double buffered.
#define ST 32
#define NTILE (Ll / ST)   // 64

__global__ __launch_bounds__(128)
void scan_k(const float* __restrict__ A_log, const float* __restrict__ Dp)
{
    __shared__ float2 du_s[2][ST][32];
    __shared__ float  z_s [2][ST][32];
    __shared__ float2 bc_s[2][ST][DSTATE];
    __shared__ float  y_s [ST][32];

    const int tid  = threadIdx.x;
    const int wid  = tid >> 5;
    const int lane = tid & 31;
    const int c    = wid * 8 + (lane >> 2);   // 0..31 channel in block
    const int q    = lane & 3;                // state group
    const int b    = blockIdx.x >> 4;
    const int d0   = (blockIdx.x & 15) * 32;
    const int d    = d0 + c;

    float A2[8];
    #pragma unroll
    for (int k = 0; k < 8; ++k)
        A2[k] = -__expf(A_log[d * DSTATE + 8 * q + k]) * 1.4426950408889634f;
    const float Dd = Dp[d];

    const size_t rowb = (size_t)b * Ll;
    const uint32_t duB = (uint32_t)__cvta_generic_to_shared(&du_s[0][0][0]);
    const uint32_t zB  = (uint32_t)__cvta_generic_to_shared(&z_s[0][0][0]);
    const uint32_t bcB = (uint32_t)__cvta_generic_to_shared(&bc_s[0][0][0]);

    // fill one tile buffer via cp.async: 1280 16B chunks, 10 per thread
#define FILL(buf, l0)                                                               \
    {                                                                               \
        _Pragma("unroll")                                                           \
        for (int cc = 0; cc < 10; ++cc) {                                           \
            int i = cc * 128 + tid;                                                 \
            if (i < 512) {                                                          \
                int row = i >> 4, off = i & 15;                                     \
                cp_async16(duB + (uint32_t)(((buf) * ST + row) * 32 + off * 2) * 8, \
                           (const char*)(sDU + (rowb + (l0) + row) * DINNER + d0) + off * 16); \
            } else if (i < 768) {                                                   \
                int ii = i - 512;                                                   \
                int row = ii >> 3, off = ii & 7;                                    \
                cp_async16(zB + (uint32_t)(((buf) * ST + row) * 32 + off * 4) * 4,  \
                           (const char*)(sZ + (rowb + (l0) + row) * DINNER + d0) + off * 16); \
            } else {                                                                \
                int ii = i - 768;                                                   \
                int row = ii >> 4, off = ii & 15;                                   \
                cp_async16(bcB + (uint32_t)(((buf) * ST + row) * DSTATE + off * 2) * 8, \
                           (const char*)(sBC + (rowb + (l0) + row) * DSTATE) + off * 16); \
            }                                                                       \
        }                                                                           \
        cp_commit();                                                                \
    }

    FILL(0, 0);
    FILL(1, ST);

    float h[8];
    #pragma unroll
    for (int k = 0; k < 8; ++k) h[k] = 0.f;

    for (int tIdx = 0; tIdx < NTILE; ++tIdx) {
        const int buf = tIdx & 1;
        cp_wait<1>();
        __syncthreads();

        #pragma unroll 4
        for (int l = 0; l < ST; ++l) {
            float2 duv = du_s[buf][l][c];
            float  zv  = z_s [buf][l][c];
            const float4* bcp = (const float4*)&bc_s[buf][l][0];
            float4 p0 = bcp[4 * q + 0];
            float4 p1 = bcp[4 * q + 1];
            float4 p2 = bcp[4 * q + 2];
            float4 p3 = bcp[4 * q + 3];

            float dtu = duv.x * duv.y;
            float y0, y1;
            {
                float e;
                e = fast_exp2(duv.x * A2[0]); h[0] = fmaf(h[0], e, dtu * p0.x);
                e = fast_exp2(duv.x * A2[1]); h[1] = fmaf(h[1], e, dtu * p0.z);
                e = fast_exp2(duv.x * A2[2]); h[2] = fmaf(h[2], e, dtu * p1.x);
                e = fast_exp2(duv.x * A2[3]); h[3] = fmaf(h[3], e, dtu * p1.z);
                e = fast_exp2(duv.x * A2[4]); h[4] = fmaf(h[4], e, dtu * p2.x);
                e = fast_exp2(duv.x * A2[5]); h[5] = fmaf(h[5], e, dtu * p2.z);
                e = fast_exp2(duv.x * A2[6]); h[6] = fmaf(h[6], e, dtu * p3.x);
                e = fast_exp2(duv.x * A2[7]); h[7] = fmaf(h[7], e, dtu * p3.z);
                y0 = h[0] * p0.y;  y1 = h[1] * p0.w;
                y0 = fmaf(h[2], p1.y, y0); y1 = fmaf(h[3], p1.w, y1);
                y0 = fmaf(h[4], p2.y, y0); y1 = fmaf(h[5], p2.w, y1);
                y0 = fmaf(h[6], p3.y, y0); y1 = fmaf(h[7], p3.w, y1);
            }
            float y = y0 + y1;
            y += __shfl_xor_sync(0xffffffffu, y, 1);
            y += __shfl_xor_sync(0xffffffffu, y, 2);

            if (q == 0) {
                y = fmaf(duv.y, Dd, y);
                float tt = fast_exp2(-1.4426950408889634f * zv);
                float g  = __fdividef(zv, 1.f + tt);
                y_s[l][c] = y * g;
            }
        }
        __syncthreads();

        // issue next-next tile into the buffer just consumed
        if (tIdx + 2 < NTILE) {
            FILL(buf, (tIdx + 2) * ST);
        } else {
            cp_commit();   // keep group count in sync for cp_wait<1>
        }

        // bulk store y tile: 32 rows x 32 ch, 2 float4 per thread
        {
            const int l0g = tIdx * ST;
            #pragma unroll
            for (int r = 0; r < 2; ++r) {
                int i   = r * 128 + tid;          // 0..255 float4 chunks
                int row = i >> 3, off = i & 7;
                *(float4*)(sY + (rowb + l0g + row) * DINNER + d0 + off * 4) =
                    *(float4*)&y_s[row][off * 4];
            }
        }
        __syncthreads();
    }
#undef FILL
}

// ---------------- launch ----------------
extern "C" void kernel_launch(void* const* d_in, const int* in_sizes, int n_in,
                              void* d_out, int out_size)
{
    const float* x      = (const float*)d_in[0];
    const float* W_in   = (const float*)d_in[1];
    const float* conv_w = (const float*)d_in[2];
    const float* conv_b = (const float*)d_in[3];
    const float* W_xprj = (const float*)d_in[4];
    const float* W_dt   = (const float*)d_in[5];
    const float* b_dt   = (const float*)d_in[6];
    const float* A_log  = (const float*)d_in[7];
    const float* Dvec   = (const float*)d_in[8];
    const float* W_out  = (const float*)d_in[9];
    const float* W_ff1  = (const float*)d_in[10];
    const float* b_ff1  = (const float*)d_in[11];
    const float* W_ff2  = (const float*)d_in[12];
    const float* b_ff2  = (const float*)d_in[13];
    float* out = (float*)d_out;

    float *pXC, *pZ, *pU, *pDTLO, *pY, *pM, *pH, *pWXP, *pWF1P;
    float2 *pDU, *pBC;
    cudaGetSymbolAddress((void**)&pXC,   sXC);
    cudaGetSymbolAddress((void**)&pZ,    sZ);
    cudaGetSymbolAddress((void**)&pU,    sU);
    cudaGetSymbolAddress((void**)&pDU,   sDU);
    cudaGetSymbolAddress((void**)&pDTLO, sDTLO);
    cudaGetSymbolAddress((void**)&pBC,   sBC);
    cudaGetSymbolAddress((void**)&pY,    sY);
    cudaGetSymbolAddress((void**)&pM,    sM);
    cudaGetSymbolAddress((void**)&pH,    sH);
    cudaGetSymbolAddress((void**)&pWXP,  sWXP);
    cudaGetSymbolAddress((void**)&pWF1P, sWF1P);

    // 0) pad small weights
    pad_wx_k <<<(128 * DINNER) / 256, 256>>>(W_xprj);
    pad_wf1_k<<<(128 * DMODEL) / 256, 256>>>(W_ff1);

    // 1) xz = x @ W_in^T -> xc/z
    {
        dim3 g((2 * DINNER) / TBN, ML / TBM);
        tgemm_k<EPI_SPLITXZ><<<g, 256>>>(x, W_in, nullptr, nullptr,
                                         ML, 2 * DINNER, DMODEL, 2 * DINNER, pXC, pZ);
    }
    // 2) conv + silu -> u
    conv_silu_k<<<(ML * DINNER / 4) / 256, 256>>>(conv_w, conv_b);

    // 3) dbc = u @ Wxproj^T -> dtlo / {B,C}
    {
        dim3 g(1, ML / TBM);
        tgemm_k<EPI_DBC><<<g, 256>>>(pU, pWXP, nullptr, pDTLO,
                                     ML, 128, DINNER, DTRANK + 2 * DSTATE, (float*)pBC, nullptr);
    }
    // 4) dt = softplus(dtlo @ W_dt^T + b_dt); writes {dt,u}
    dt_k<<<ML / DT_ROWS, DINNER>>>(W_dt, b_dt);

    // 5) selective scan (smem pipelined)
    scan_k<<<Bb * (DINNER / 32), 128>>>(A_log, Dvec);

    // 6) m = y @ W_out^T
    {
        dim3 g(DMODEL / TBN, ML / TBM);
        tgemm_k<EPI_PLAIN><<<g, 256>>>(pY, W_out, nullptr, pM,
                                       ML, DMODEL, DINNER, DMODEL, nullptr, nullptr);
    }
    // 7) h = leaky_relu(m @ W_ff1^T + b_ff1)
    {
        dim3 g(1, ML / TBM);
        tgemm_k<EPI_LEAKY><<<g, 256>>>(pM, pWF1P, b_ff1, pH,
                                       ML, 128, DMODEL, HMLP, nullptr, nullptr);
    }
    // 8) out = sigmoid(h @ W_ff2^T + b_ff2)
    {
        dim3 g(BINS / TBN, ML / TBM);
        tgemm_k<EPI_SIGMOID><<<g, 256>>>(pH, W_ff2, b_ff2, out,
                                         ML, BINS, HMLP, BINS, nullptr, nullptr);
    }
}